// round 14
// baseline (speedup 1.0000x reference)
#include <cuda_runtime.h>
#include <cuda_bf16.h>
#include <cstdint>

// ---------------------------------------------------------------------------
// WindowedMultiHeadAttention — bf16 mma.sync; PERSISTENT GEMM CTAs (296),
// cross-tile pipelined 3-stage cp.async ring; 64x64 warp tiles, 2 CTAs/SM.
// ---------------------------------------------------------------------------

#define EMB   768
#define NH    8
#define HD    96
#define NWIN  256
#define NTOK  196
#define MROWS (NWIN * NTOK)   // 50176
#define QKVC  (3 * EMB)       // 2304

#define NCTA  296             // 148 SMs x 2
#define NTX1  18               // gemm1 n-tiles
#define NT1   (NTX1 * 392)     // 7056 tiles
#define NTX3  6                // gemm3 n-tiles
#define NT3   (NTX3 * 392)     // 2352 tiles

__device__ __align__(16) __nv_bfloat16 g_Qb[NWIN * NH * NTOK * HD];
__device__ __align__(16) __nv_bfloat16 g_Kb[NWIN * NH * NTOK * HD];
__device__ __align__(16) __nv_bfloat16 g_Vb[NWIN * NH * NTOK * HD];
__device__ __align__(16) __nv_bfloat16 g_A1[MROWS * EMB];
__device__ __align__(16) __nv_bfloat16 g_W1[QKVC * EMB];    // permuted [s][h][dd], K-major
__device__ __align__(16) __nv_bfloat16 g_W2[EMB * EMB];
__device__ __align__(16) __nv_bfloat16 g_Ob[MROWS * EMB];
__device__ float g_b1p[QKVC];

__device__ __forceinline__ int map_row(int r) {
    int win = r / NTOK;
    int t   = r - win * NTOK;
    int b   = win >> 4;
    int wr  = win & 15;
    int wh  = wr >> 2;
    int ww  = wr & 3;
    int i   = t / 14;
    int j   = t - i * 14;
    return (b * 56 + wh * 14 + i) * 56 + (ww * 14 + j);
}

__device__ __forceinline__ uint32_t pk(float x, float y) {
    __nv_bfloat162 h = __floats2bfloat162_rn(x, y);
    return *reinterpret_cast<uint32_t*>(&h);
}

__device__ __forceinline__ void cp16(uint32_t dst, const void* src) {
    asm volatile("cp.async.cg.shared.global [%0], [%1], 16;" :: "r"(dst), "l"(src));
}
__device__ __forceinline__ void cp_commit() {
    asm volatile("cp.async.commit_group;");
}
template <int N>
__device__ __forceinline__ void cp_wait() {
    asm volatile("cp.async.wait_group %0;" :: "n"(N));
}

__device__ __forceinline__ void ldsm4(uint32_t* r, uint32_t addr) {
    asm volatile("ldmatrix.sync.aligned.m8n8.x4.shared.b16 {%0,%1,%2,%3}, [%4];"
                 : "=r"(r[0]), "=r"(r[1]), "=r"(r[2]), "=r"(r[3]) : "r"(addr));
}
__device__ __forceinline__ void ldsm4t(uint32_t* r, uint32_t addr) {
    asm volatile("ldmatrix.sync.aligned.m8n8.x4.trans.shared.b16 {%0,%1,%2,%3}, [%4];"
                 : "=r"(r[0]), "=r"(r[1]), "=r"(r[2]), "=r"(r[3]) : "r"(addr));
}

__device__ __forceinline__ void mma_bf16(float* d, const uint32_t* a, uint32_t b0, uint32_t b1) {
    asm volatile(
        "mma.sync.aligned.m16n8k16.row.col.f32.bf16.bf16.f32 "
        "{%0,%1,%2,%3}, {%4,%5,%6,%7}, {%8,%9}, {%0,%1,%2,%3};"
        : "+f"(d[0]), "+f"(d[1]), "+f"(d[2]), "+f"(d[3])
        : "r"(a[0]), "r"(a[1]), "r"(a[2]), "r"(a[3]), "r"(b0), "r"(b1));
}

// ---------------------------------------------------------------------------
// prep kernels
// ---------------------------------------------------------------------------
__global__ void conv_x_kernel(const float* __restrict__ x) {
    int g  = blockIdx.x * 256 + threadIdx.x;
    int r  = g / 96;
    int kc = (g - r * 96) * 8;
    const float* s = x + (size_t)map_row(r) * EMB + kc;
    float4 v0 = *(const float4*)s;
    float4 v1 = *(const float4*)(s + 4);
    uint4 u;
    u.x = pk(v0.x, v0.y); u.y = pk(v0.z, v0.w);
    u.z = pk(v1.x, v1.y); u.w = pk(v1.z, v1.w);
    *(uint4*)(g_A1 + (size_t)r * EMB + kc) = u;
}

__global__ void conv_w1_kernel(const float* __restrict__ w,
                               const float* __restrict__ b) {
    int g  = blockIdx.x * 256 + threadIdx.x;
    int c  = g / 96;
    int k0 = (g - c * 96) * 8;
    int h  = c / 288;
    int rm = c - h * 288;
    int dd = rm / 3;
    int s  = rm - dd * 3;
    int cp_ = s * 768 + h * 96 + dd;
    float v[8];
#pragma unroll
    for (int i = 0; i < 8; i++) v[i] = w[(size_t)(k0 + i) * QKVC + c];
    uint4 u;
    u.x = pk(v[0], v[1]); u.y = pk(v[2], v[3]);
    u.z = pk(v[4], v[5]); u.w = pk(v[6], v[7]);
    *(uint4*)(g_W1 + (size_t)cp_ * EMB + k0) = u;
    if (g < QKVC) {
        int ch  = g / 288;
        int crm = g - ch * 288;
        int cdd = crm / 3;
        int cs  = crm - cdd * 3;
        g_b1p[cs * 768 + ch * 96 + cdd] = b[g];
    }
}

__global__ void conv_w2_kernel(const float* __restrict__ w) {
    int g  = blockIdx.x * 256 + threadIdx.x;
    int c  = g / 96;
    int k0 = (g - c * 96) * 8;
    float v[8];
#pragma unroll
    for (int i = 0; i < 8; i++) v[i] = w[(size_t)(k0 + i) * EMB + c];
    uint4 u;
    u.x = pk(v[0], v[1]); u.y = pk(v[2], v[3]);
    u.z = pk(v[4], v[5]); u.w = pk(v[6], v[7]);
    *(uint4*)(g_W2 + (size_t)c * EMB + k0) = u;
}

// ---------------------------------------------------------------------------
// Persistent bf16 GEMM: each CTA loops tiles { cta + j*NCTA }, 128x128 tile,
// 4 warps of 64x64, BK=64, 3-stage ring pipelined ACROSS tile boundaries.
// ---------------------------------------------------------------------------
#define STG 32768
#define GSMEM (3 * STG + 128)

// fill stage `fs` with chunk g (tile = cta + (g/12)*NCTA, kc = (g%12)*64)
template <int NTX>
__device__ __forceinline__ void fill_g(uint32_t sb, int fs, int cta, int g,
                                       const __nv_bfloat16* __restrict__ A,
                                       const __nv_bfloat16* __restrict__ B,
                                       int tid) {
    const int tl   = g / 12;
    const int tile = cta + tl * NCTA;
    const int kc   = (g - tl * 12) * 64;
    const int mt   = tile / NTX;
    const int m0   = mt * 128;
    const int n0   = (tile - mt * NTX) * 128;
    uint32_t abase = sb + fs * STG;
    uint32_t bbase = abase + 16384;
#pragma unroll
    for (int i = 0; i < 8; i++) {
        int idx = tid + i * 128;
        int r = idx >> 3, c = idx & 7;
        uint32_t sw = (uint32_t)(r * 128 + ((c ^ (r & 7)) << 4));
        cp16(abase + sw, A + (size_t)(m0 + r) * EMB + kc + c * 8);
    }
#pragma unroll
    for (int i = 0; i < 8; i++) {
        int idx = tid + i * 128;
        int r = idx >> 3, c = idx & 7;
        uint32_t sw = (uint32_t)(r * 128 + ((c ^ (r & 7)) << 4));
        cp16(bbase + sw, B + (size_t)(n0 + r) * EMB + kc + c * 8);
    }
}

// ---------------------------------------------------------------------------
// GEMM1 persistent
// ---------------------------------------------------------------------------
__global__ void __launch_bounds__(128, 2)
gemm1_kernel() {
    extern __shared__ __align__(16) char dsm[];
    uint32_t sb0 = (uint32_t)__cvta_generic_to_shared(dsm);
    const uint32_t sb = (sb0 + 127) & ~127u;
    const int tid = threadIdx.x;
    const int cta = blockIdx.x;
    const int ntloc = (NT1 - cta + NCTA - 1) / NCTA;
    const int L = ntloc * 12;

    const int wid = tid >> 5, lane = tid & 31;
    const int wm = (wid >> 1) * 64;
    const int wn = (wid & 1) * 64;
    const int lr = lane & 15;
    const uint32_t khx = (uint32_t)((lane >> 4) << 4);
    const int gid = lane >> 2, tig = lane & 3;

    uint32_t arel[4], brel[4];
#pragma unroll
    for (int mf = 0; mf < 4; mf++) {
        int r = wm + mf * 16 + lr;
        arel[mf] = ((uint32_t)(r * 128 + ((r & 7) << 4))) ^ khx;
    }
#pragma unroll
    for (int nt = 0; nt < 4; nt++) {
        int r = wn + nt * 16 + lr;
        brel[nt] = ((uint32_t)(16384 + r * 128 + ((r & 7) << 4))) ^ khx;
    }

    float acc[4][8][4];
#pragma unroll
    for (int i = 0; i < 4; i++)
#pragma unroll
        for (int j = 0; j < 8; j++)
#pragma unroll
            for (int q = 0; q < 4; q++) acc[i][j][q] = 0.f;

    fill_g<NTX1>(sb, 0, cta, 0, g_A1, g_W1, tid); cp_commit();
    fill_g<NTX1>(sb, 1, cta, 1, g_A1, g_W1, tid); cp_commit();

    int st = 0, fs = 2;
#pragma unroll 1
    for (int l = 0; l < L; l++) {
        cp_wait<1>();
        __syncthreads();
        if (l + 2 < L) fill_g<NTX1>(sb, fs, cta, l + 2, g_A1, g_W1, tid);
        cp_commit();
        const uint32_t stb = sb + (uint32_t)st * STG;

#pragma unroll
        for (int kk = 0; kk < 4; kk++) {
            const uint32_t kx = (uint32_t)(kk << 5);
            uint32_t a[4][4], b[4][4];
#pragma unroll
            for (int mf = 0; mf < 4; mf++) ldsm4(a[mf], (stb + arel[mf]) ^ kx);
#pragma unroll
            for (int nt = 0; nt < 4; nt++) ldsm4(b[nt], (stb + brel[nt]) ^ kx);
#pragma unroll
            for (int mf = 0; mf < 4; mf++)
#pragma unroll
                for (int nt = 0; nt < 4; nt++) {
                    mma_bf16(acc[mf][nt * 2],     a[mf], b[nt][0], b[nt][2]);
                    mma_bf16(acc[mf][nt * 2 + 1], a[mf], b[nt][1], b[nt][3]);
                }
        }
        st = (st == 2) ? 0 : st + 1;
        fs = (fs == 2) ? 0 : fs + 1;

        if ((l % 12) == 11) {
            // epilogue for tile just finished (overlaps in-flight prefetch)
            const int tile = cta + (l / 12) * NCTA;
            const int mt   = tile / NTX1;
            const int m0   = mt * 128;
            const int n0   = (tile - mt * NTX1) * 128;
#pragma unroll
            for (int mf = 0; mf < 4; mf++) {
#pragma unroll
                for (int q2 = 0; q2 < 2; q2++) {
                    const int r = m0 + wm + mf * 16 + gid + q2 * 8;
                    const int win = r / NTOK;
                    const int t = r - win * NTOK;
#pragma unroll
                    for (int nf = 0; nf < 8; nf++) {
                        const int c = n0 + wn + nf * 8 + tig * 2;
                        const int s  = c / 768;
                        const int rm = c - s * 768;
                        const int h  = rm / 96;
                        const int dd = rm - h * 96;
                        float v0 = acc[mf][nf][q2 * 2]     + g_b1p[c];
                        float v1 = acc[mf][nf][q2 * 2 + 1] + g_b1p[c + 1];
                        __nv_bfloat16* base = (s == 0 ? g_Qb : (s == 1 ? g_Kb : g_Vb))
                                              + ((size_t)(win * NH + h) * NTOK + t) * HD + dd;
                        *(uint32_t*)base = pk(v0, v1);
                        acc[mf][nf][q2 * 2] = 0.f;
                        acc[mf][nf][q2 * 2 + 1] = 0.f;
                    }
                }
            }
        }
    }
}

// ---------------------------------------------------------------------------
// GEMM3 persistent
// ---------------------------------------------------------------------------
__global__ void __launch_bounds__(128, 2)
gemm3_kernel(const float* __restrict__ x,
             const float* __restrict__ bias,
             float* __restrict__ out) {
    extern __shared__ __align__(16) char dsm[];
    uint32_t sb0 = (uint32_t)__cvta_generic_to_shared(dsm);
    const uint32_t sb = (sb0 + 127) & ~127u;
    const int tid = threadIdx.x;
    const int cta = blockIdx.x;
    const int ntloc = (NT3 - cta + NCTA - 1) / NCTA;
    const int L = ntloc * 12;
    if (L <= 0) return;

    const int wid = tid >> 5, lane = tid & 31;
    const int wm = (wid >> 1) * 64;
    const int wn = (wid & 1) * 64;
    const int lr = lane & 15;
    const uint32_t khx = (uint32_t)((lane >> 4) << 4);
    const int gid = lane >> 2, tig = lane & 3;

    uint32_t arel[4], brel[4];
#pragma unroll
    for (int mf = 0; mf < 4; mf++) {
        int r = wm + mf * 16 + lr;
        arel[mf] = ((uint32_t)(r * 128 + ((r & 7) << 4))) ^ khx;
    }
#pragma unroll
    for (int nt = 0; nt < 4; nt++) {
        int r = wn + nt * 16 + lr;
        brel[nt] = ((uint32_t)(16384 + r * 128 + ((r & 7) << 4))) ^ khx;
    }

    float acc[4][8][4];
#pragma unroll
    for (int i = 0; i < 4; i++)
#pragma unroll
        for (int j = 0; j < 8; j++)
#pragma unroll
            for (int q = 0; q < 4; q++) acc[i][j][q] = 0.f;

    fill_g<NTX3>(sb, 0, cta, 0, g_Ob, g_W2, tid); cp_commit();
    fill_g<NTX3>(sb, 1, cta, 1, g_Ob, g_W2, tid); cp_commit();

    int st = 0, fs = 2;
#pragma unroll 1
    for (int l = 0; l < L; l++) {
        cp_wait<1>();
        __syncthreads();
        if (l + 2 < L) fill_g<NTX3>(sb, fs, cta, l + 2, g_Ob, g_W2, tid);
        cp_commit();
        const uint32_t stb = sb + (uint32_t)st * STG;

#pragma unroll
        for (int kk = 0; kk < 4; kk++) {
            const uint32_t kx = (uint32_t)(kk << 5);
            uint32_t a[4][4], b[4][4];
#pragma unroll
            for (int mf = 0; mf < 4; mf++) ldsm4(a[mf], (stb + arel[mf]) ^ kx);
#pragma unroll
            for (int nt = 0; nt < 4; nt++) ldsm4(b[nt], (stb + brel[nt]) ^ kx);
#pragma unroll
            for (int mf = 0; mf < 4; mf++)
#pragma unroll
                for (int nt = 0; nt < 4; nt++) {
                    mma_bf16(acc[mf][nt * 2],     a[mf], b[nt][0], b[nt][2]);
                    mma_bf16(acc[mf][nt * 2 + 1], a[mf], b[nt][1], b[nt][3]);
                }
        }
        st = (st == 2) ? 0 : st + 1;
        fs = (fs == 2) ? 0 : fs + 1;

        if ((l % 12) == 11) {
            const int tile = cta + (l / 12) * NCTA;
            const int mt   = tile / NTX3;
            const int m0   = mt * 128;
            const int n0   = (tile - mt * NTX3) * 128;
#pragma unroll
            for (int mf = 0; mf < 4; mf++) {
#pragma unroll
                for (int q2 = 0; q2 < 2; q2++) {
                    const int r = m0 + wm + mf * 16 + gid + q2 * 8;
                    const int xr = map_row(r);
#pragma unroll
                    for (int nf = 0; nf < 8; nf++) {
                        const int c = n0 + wn + nf * 8 + tig * 2;
                        const size_t idx = (size_t)xr * EMB + c;
                        float2 xv = *(const float2*)(x + idx);
                        out[idx]     = acc[mf][nf][q2 * 2]     + bias[c]     + xv.x;
                        out[idx + 1] = acc[mf][nf][q2 * 2 + 1] + bias[c + 1] + xv.y;
                        acc[mf][nf][q2 * 2] = 0.f;
                        acc[mf][nf][q2 * 2 + 1] = 0.f;
                    }
                }
            }
        }
    }
}

// ---------------------------------------------------------------------------
// Attention (unchanged): grid (2048, 2), 128 threads, 2 CTAs/SM.
// ---------------------------------------------------------------------------
#define KVSTRIDE 208
#define KV_BYTES (224 * KVSTRIDE)
#define SHIFT 40.0f

__global__ void __launch_bounds__(128, 2)
attn_kernel() {
    extern __shared__ __align__(16) char smem[];
    const int wh   = blockIdx.x;
    const int half = blockIdx.y;
    const int tid  = threadIdx.x;
    const uint32_t sb = (uint32_t)__cvta_generic_to_shared(smem);
    const uint32_t Ko = sb, Vo = sb + KV_BYTES;

    const __nv_bfloat16* gq = g_Qb + (size_t)wh * NTOK * HD;
    const __nv_bfloat16* gk = g_Kb + (size_t)wh * NTOK * HD;
    const __nv_bfloat16* gv = g_Vb + (size_t)wh * NTOK * HD;

    for (int i = tid; i < NTOK * 12; i += 128) {
        int t = i / 12, c = i - (i / 12) * 12;
        uint32_t off = (uint32_t)(t * KVSTRIDE + c * 16);
        const size_t g = (size_t)t * HD + c * 8;
        cp16(Ko + off, gk + g);
        cp16(Vo + off, gv + g);
    }
    cp_commit();
    for (int i = tid; i < 28 * 12; i += 128) {
        int t = 196 + i / 12, c = i - (i / 12) * 12;
        uint32_t off = (uint32_t)(t * KVSTRIDE + c * 16);
        uint4 z = make_uint4(0, 0, 0, 0);
        *(uint4*)(smem + off) = z;
        *(uint4*)(smem + KV_BYTES + off) = z;
    }

    const int w = tid >> 5;
    const int lane = tid & 31;
    const int gid = lane >> 2, tig = lane & 3;
    const int m0 = half * 128 + w * 32;
    const bool act = (m0 < NTOK);

    uint32_t aq[2][6][4];
    if (act) {
#pragma unroll
        for (int mt = 0; mt < 2; mt++) {
            const int r0 = m0 + mt * 16 + gid;
            const int r1 = r0 + 8;
#pragma unroll
            for (int kk = 0; kk < 6; kk++) {
                const int col = kk * 16 + tig * 2;
                aq[mt][kk][0] = (r0 < NTOK) ? *(const uint32_t*)(gq + (size_t)r0 * HD + col) : 0u;
                aq[mt][kk][1] = (r1 < NTOK) ? *(const uint32_t*)(gq + (size_t)r1 * HD + col) : 0u;
                aq[mt][kk][2] = (r0 < NTOK) ? *(const uint32_t*)(gq + (size_t)r0 * HD + col + 8) : 0u;
                aq[mt][kk][3] = (r1 < NTOK) ? *(const uint32_t*)(gq + (size_t)r1 * HD + col + 8) : 0u;
            }
        }
    }

    cp_wait<0>();
    __syncthreads();

    if (!act) return;

    float accO[2][12][4];
#pragma unroll
    for (int mt = 0; mt < 2; mt++)
#pragma unroll
        for (int nt = 0; nt < 12; nt++)
#pragma unroll
            for (int q = 0; q < 4; q++) accO[mt][nt][q] = 0.f;

    float rl[2][2] = {{0.f, 0.f}, {0.f, 0.f}};

#pragma unroll 1
    for (int ch = 0; ch < 7; ch++) {
        const int n0 = ch * 32;
        float s[2][4][4];
#pragma unroll
        for (int mt = 0; mt < 2; mt++)
#pragma unroll
            for (int nt = 0; nt < 4; nt++)
#pragma unroll
                for (int q = 0; q < 4; q++) s[mt][nt][q] = 0.f;

#pragma unroll
        for (int kk = 0; kk < 6; kk++) {
            uint32_t kb0[4], kb1[4];
            uint32_t kaddr = Ko + (uint32_t)((n0 + (lane & 7) + ((lane >> 4) << 3)) * KVSTRIDE
                                             + (kk * 2 + ((lane >> 3) & 1)) * 16);
            ldsm4(kb0, kaddr);
            ldsm4(kb1, kaddr + 16 * KVSTRIDE);
#pragma unroll
            for (int mt = 0; mt < 2; mt++) {
                mma_bf16(s[mt][0], aq[mt][kk], kb0[0], kb0[1]);
                mma_bf16(s[mt][1], aq[mt][kk], kb0[2], kb0[3]);
                mma_bf16(s[mt][2], aq[mt][kk], kb1[0], kb1[1]);
                mma_bf16(s[mt][3], aq[mt][kk], kb1[2], kb1[3]);
            }
        }

        if (ch == 6) {
#pragma unroll
            for (int mt = 0; mt < 2; mt++)
#pragma unroll
                for (int nt = 0; nt < 4; nt++)
#pragma unroll
                    for (int q = 0; q < 4; q++) {
                        int col = n0 + nt * 8 + tig * 2 + (q & 1);
                        if (col >= NTOK) s[mt][nt][q] = -1e30f;
                    }
        }

#pragma unroll
        for (int mt = 0; mt < 2; mt++) {
#pragma unroll
            for (int hf = 0; hf < 2; hf++) {
                float ls = 0.f;
#pragma unroll
                for (int nt = 0; nt < 4; nt++) {
                    float p0 = __expf(s[mt][nt][hf * 2]     - SHIFT);
                    float p1 = __expf(s[mt][nt][hf * 2 + 1] - SHIFT);
                    s[mt][nt][hf * 2]     = p0;
                    s[mt][nt][hf * 2 + 1] = p1;
                    ls += p0 + p1;
                }
                rl[mt][hf] += ls;
            }
        }

#pragma unroll
        for (int kk = 0; kk < 2; kk++) {
            uint32_t ap[2][4];
#pragma unroll
            for (int mt = 0; mt < 2; mt++) {
                ap[mt][0] = pk(s[mt][kk * 2][0], s[mt][kk * 2][1]);
                ap[mt][1] = pk(s[mt][kk * 2][2], s[mt][kk * 2][3]);
                ap[mt][2] = pk(s[mt][kk * 2 + 1][0], s[mt][kk * 2 + 1][1]);
                ap[mt][3] = pk(s[mt][kk * 2 + 1][2], s[mt][kk * 2 + 1][3]);
            }
#pragma unroll
            for (int u = 0; u < 6; u++) {
                uint32_t vb[4];
                ldsm4t(vb, Vo + (uint32_t)((n0 + kk * 16 + (lane & 7) + (((lane >> 3) & 1) << 3)) * KVSTRIDE
                                           + (u * 2 + (lane >> 4)) * 16));
#pragma unroll
                for (int mt = 0; mt < 2; mt++) {
                    mma_bf16(accO[mt][u * 2],     ap[mt], vb[0], vb[1]);
                    mma_bf16(accO[mt][u * 2 + 1], ap[mt], vb[2], vb[3]);
                }
            }
        }
    }

    const int win = wh >> 3;
    const int h   = wh & 7;
#pragma unroll
    for (int mt = 0; mt < 2; mt++) {
#pragma unroll
        for (int hf = 0; hf < 2; hf++) {
            float tot = rl[mt][hf];
            tot += __shfl_xor_sync(0xffffffff, tot, 1);
            tot += __shfl_xor_sync(0xffffffff, tot, 2);
            const int t = m0 + mt * 16 + gid + hf * 8;
            if (t < NTOK) {
                const float inv = 1.0f / (tot * 27.712812921102035f);
                uint32_t* op = (uint32_t*)(g_Ob + ((size_t)(win * NTOK + t)) * EMB
                                           + h * HD + tig * 2);
#pragma unroll
                for (int nt = 0; nt < 12; nt++) {
                    op[nt * 4] = pk(accO[mt][nt][hf * 2] * inv,
                                    accO[mt][nt][hf * 2 + 1] * inv);
                }
            }
        }
    }
}

// ---------------------------------------------------------------------------
extern "C" void kernel_launch(void* const* d_in, const int* in_sizes, int n_in,
                              void* d_out, int out_size) {
    const float* x      = (const float*)d_in[0];
    const float* w_qkv  = (const float*)d_in[1];
    const float* b_qkv  = (const float*)d_in[2];
    const float* w_proj = (const float*)d_in[3];
    const float* b_proj = (const float*)d_in[4];
    float* out = (float*)d_out;

    conv_x_kernel<<<MROWS * 96 / 256, 256>>>(x);
    conv_w1_kernel<<<QKVC * 96 / 256, 256>>>(w_qkv, b_qkv);
    conv_w2_kernel<<<EMB * 96 / 256, 256>>>(w_proj);

    cudaFuncSetAttribute(gemm1_kernel, cudaFuncAttributeMaxDynamicSharedMemorySize, GSMEM);
    gemm1_kernel<<<NCTA, 128, GSMEM>>>();

    const int asmem = 2 * KV_BYTES;
    cudaFuncSetAttribute(attn_kernel, cudaFuncAttributeMaxDynamicSharedMemorySize, asmem);
    attn_kernel<<<dim3(NWIN * NH, 2), 128, asmem>>>();

    cudaFuncSetAttribute(gemm3_kernel, cudaFuncAttributeMaxDynamicSharedMemorySize, GSMEM);
    gemm3_kernel<<<NCTA, 128, GSMEM>>>(x, b_proj, out);
}

// round 15
// speedup vs baseline: 1.1029x; 1.1029x over previous
#include <cuda_runtime.h>
#include <cuda_bf16.h>
#include <cstdint>

// ---------------------------------------------------------------------------
// WindowedMultiHeadAttention — bf16 mma.sync; champion GEMM config (R10/R11:
// 128-thr CTAs, 64x64 warps, 2 CTAs/SM) + single merged prep kernel.
// ---------------------------------------------------------------------------

#define EMB   768
#define NH    8
#define HD    96
#define NWIN  256
#define NTOK  196
#define MROWS (NWIN * NTOK)   // 50176
#define QKVC  (3 * EMB)       // 2304

#define PB1 (MROWS * 96 / 256)            // 18816 blocks: x gather
#define PB2 (QKVC * 96 / 256)             // 864 blocks: w1 permute (+bias)
#define PB3 (EMB * 96 / 256)              // 288 blocks: w2 transpose

__device__ __align__(16) __nv_bfloat16 g_Qb[NWIN * NH * NTOK * HD];
__device__ __align__(16) __nv_bfloat16 g_Kb[NWIN * NH * NTOK * HD];
__device__ __align__(16) __nv_bfloat16 g_Vb[NWIN * NH * NTOK * HD];
__device__ __align__(16) __nv_bfloat16 g_A1[MROWS * EMB];
__device__ __align__(16) __nv_bfloat16 g_W1[QKVC * EMB];    // permuted [s][h][dd], K-major
__device__ __align__(16) __nv_bfloat16 g_W2[EMB * EMB];
__device__ __align__(16) __nv_bfloat16 g_Ob[MROWS * EMB];
__device__ float g_b1p[QKVC];

__device__ __forceinline__ int map_row(int r) {
    int win = r / NTOK;
    int t   = r - win * NTOK;
    int b   = win >> 4;
    int wr  = win & 15;
    int wh  = wr >> 2;
    int ww  = wr & 3;
    int i   = t / 14;
    int j   = t - i * 14;
    return (b * 56 + wh * 14 + i) * 56 + (ww * 14 + j);
}

__device__ __forceinline__ uint32_t pk(float x, float y) {
    __nv_bfloat162 h = __floats2bfloat162_rn(x, y);
    return *reinterpret_cast<uint32_t*>(&h);
}

__device__ __forceinline__ void cp16(uint32_t dst, const void* src) {
    asm volatile("cp.async.cg.shared.global [%0], [%1], 16;" :: "r"(dst), "l"(src));
}
__device__ __forceinline__ void cp_commit() {
    asm volatile("cp.async.commit_group;");
}
template <int N>
__device__ __forceinline__ void cp_wait() {
    asm volatile("cp.async.wait_group %0;" :: "n"(N));
}

__device__ __forceinline__ void ldsm4(uint32_t* r, uint32_t addr) {
    asm volatile("ldmatrix.sync.aligned.m8n8.x4.shared.b16 {%0,%1,%2,%3}, [%4];"
                 : "=r"(r[0]), "=r"(r[1]), "=r"(r[2]), "=r"(r[3]) : "r"(addr));
}
__device__ __forceinline__ void ldsm4t(uint32_t* r, uint32_t addr) {
    asm volatile("ldmatrix.sync.aligned.m8n8.x4.trans.shared.b16 {%0,%1,%2,%3}, [%4];"
                 : "=r"(r[0]), "=r"(r[1]), "=r"(r[2]), "=r"(r[3]) : "r"(addr));
}

__device__ __forceinline__ void mma_bf16(float* d, const uint32_t* a, uint32_t b0, uint32_t b1) {
    asm volatile(
        "mma.sync.aligned.m16n8k16.row.col.f32.bf16.bf16.f32 "
        "{%0,%1,%2,%3}, {%4,%5,%6,%7}, {%8,%9}, {%0,%1,%2,%3};"
        : "+f"(d[0]), "+f"(d[1]), "+f"(d[2]), "+f"(d[3])
        : "r"(a[0]), "r"(a[1]), "r"(a[2]), "r"(a[3]), "r"(b0), "r"(b1));
}

// ---------------------------------------------------------------------------
// merged prep kernel: block range selects task
// ---------------------------------------------------------------------------
__global__ void prep_kernel(const float* __restrict__ x,
                            const float* __restrict__ w_qkv,
                            const float* __restrict__ b_qkv,
                            const float* __restrict__ w_proj) {
    const int blk = blockIdx.x;
    const int tid = threadIdx.x;

    if (blk < PB1) {
        // gather x -> g_A1 bf16
        int g  = blk * 256 + tid;
        int r  = g / 96;
        int kc = (g - r * 96) * 8;
        const float* s = x + (size_t)map_row(r) * EMB + kc;
        float4 v0 = *(const float4*)s;
        float4 v1 = *(const float4*)(s + 4);
        uint4 u;
        u.x = pk(v0.x, v0.y); u.y = pk(v0.z, v0.w);
        u.z = pk(v1.x, v1.y); u.w = pk(v1.z, v1.w);
        *(uint4*)(g_A1 + (size_t)r * EMB + kc) = u;
    } else if (blk < PB1 + PB2) {
        // w_qkv permute+transpose -> g_W1; bias permute -> g_b1p
        int g  = (blk - PB1) * 256 + tid;
        int c  = g / 96;
        int k0 = (g - c * 96) * 8;
        int h  = c / 288;
        int rm = c - h * 288;
        int dd = rm / 3;
        int s  = rm - dd * 3;
        int cp_ = s * 768 + h * 96 + dd;
        float v[8];
#pragma unroll
        for (int i = 0; i < 8; i++) v[i] = w_qkv[(size_t)(k0 + i) * QKVC + c];
        uint4 u;
        u.x = pk(v[0], v[1]); u.y = pk(v[2], v[3]);
        u.z = pk(v[4], v[5]); u.w = pk(v[6], v[7]);
        *(uint4*)(g_W1 + (size_t)cp_ * EMB + k0) = u;
        if (g < QKVC) {
            int ch  = g / 288;
            int crm = g - ch * 288;
            int cdd = crm / 3;
            int cs  = crm - cdd * 3;
            g_b1p[cs * 768 + ch * 96 + cdd] = b_qkv[g];
        }
    } else {
        // w_proj transpose -> g_W2
        int g  = (blk - PB1 - PB2) * 256 + tid;
        int c  = g / 96;
        int k0 = (g - c * 96) * 8;
        float v[8];
#pragma unroll
        for (int i = 0; i < 8; i++) v[i] = w_proj[(size_t)(k0 + i) * EMB + c];
        uint4 u;
        u.x = pk(v[0], v[1]); u.y = pk(v[2], v[3]);
        u.z = pk(v[4], v[5]); u.w = pk(v[6], v[7]);
        *(uint4*)(g_W2 + (size_t)c * EMB + k0) = u;
    }
}

// ---------------------------------------------------------------------------
// bf16 GEMM mainloop (R11 champion): C[128m x 128n] = A[128,K=768] @ B[128,K]^T
// 128 threads = 4 warps of 64x64 (2x2). BK=64, 3-stage cp.async, 2 CTAs/SM.
// ---------------------------------------------------------------------------
#define STG 32768
#define GSMEM (3 * STG + 128)

__device__ __forceinline__ void g_fill(uint32_t sb, int stage,
                                       const __nv_bfloat16* __restrict__ A,
                                       const __nv_bfloat16* __restrict__ B,
                                       int m0, int n0, int kc, int tid) {
    uint32_t abase = sb + stage * STG;
    uint32_t bbase = abase + 16384;
#pragma unroll
    for (int i = 0; i < 8; i++) {
        int idx = tid + i * 128;
        int r = idx >> 3, c = idx & 7;
        uint32_t sw = (uint32_t)(r * 128 + ((c ^ (r & 7)) << 4));
        cp16(abase + sw, A + (size_t)(m0 + r) * EMB + kc + c * 8);
    }
#pragma unroll
    for (int i = 0; i < 8; i++) {
        int idx = tid + i * 128;
        int r = idx >> 3, c = idx & 7;
        uint32_t sw = (uint32_t)(r * 128 + ((c ^ (r & 7)) << 4));
        cp16(bbase + sw, B + (size_t)(n0 + r) * EMB + kc + c * 8);
    }
}

__device__ __forceinline__ void gemm_main(const __nv_bfloat16* __restrict__ A,
                                          const __nv_bfloat16* __restrict__ B,
                                          int m0, int n0,
                                          float (&acc)[4][8][4]) {
    extern __shared__ __align__(16) char dsm[];
    uint32_t sb0 = (uint32_t)__cvta_generic_to_shared(dsm);
    const uint32_t sb = (sb0 + 127) & ~127u;
    const int tid = threadIdx.x;

#pragma unroll
    for (int i = 0; i < 4; i++)
#pragma unroll
        for (int j = 0; j < 8; j++)
#pragma unroll
            for (int q = 0; q < 4; q++) acc[i][j][q] = 0.f;

    const int wid = tid >> 5, lane = tid & 31;
    const int wm = (wid >> 1) * 64;
    const int wn = (wid & 1) * 64;
    const int lr = lane & 15;
    const uint32_t khx = (uint32_t)((lane >> 4) << 4);

    uint32_t arel[4], brel[4];
#pragma unroll
    for (int mf = 0; mf < 4; mf++) {
        int r = wm + mf * 16 + lr;
        arel[mf] = ((uint32_t)(r * 128 + ((r & 7) << 4))) ^ khx;
    }
#pragma unroll
    for (int nt = 0; nt < 4; nt++) {
        int r = wn + nt * 16 + lr;
        brel[nt] = ((uint32_t)(16384 + r * 128 + ((r & 7) << 4))) ^ khx;
    }

    g_fill(sb, 0, A, B, m0, n0, 0, tid);  cp_commit();
    g_fill(sb, 1, A, B, m0, n0, 64, tid); cp_commit();

    int st = 0, fs = 2;
#pragma unroll 1
    for (int it = 0; it < 12; it++) {
        cp_wait<1>();
        __syncthreads();
        if (it + 2 < 12) g_fill(sb, fs, A, B, m0, n0, (it + 2) * 64, tid);
        cp_commit();
        const uint32_t stb = sb + (uint32_t)st * STG;

#pragma unroll
        for (int kk = 0; kk < 4; kk++) {
            const uint32_t kx = (uint32_t)(kk << 5);
            uint32_t a[4][4], b[4][4];
#pragma unroll
            for (int mf = 0; mf < 4; mf++) ldsm4(a[mf], (stb + arel[mf]) ^ kx);
#pragma unroll
            for (int nt = 0; nt < 4; nt++) ldsm4(b[nt], (stb + brel[nt]) ^ kx);
#pragma unroll
            for (int mf = 0; mf < 4; mf++)
#pragma unroll
                for (int nt = 0; nt < 4; nt++) {
                    mma_bf16(acc[mf][nt * 2],     a[mf], b[nt][0], b[nt][2]);
                    mma_bf16(acc[mf][nt * 2 + 1], a[mf], b[nt][1], b[nt][3]);
                }
        }
        st = (st == 2) ? 0 : st + 1;
        fs = (fs == 2) ? 0 : fs + 1;
    }
}

__global__ void __launch_bounds__(128, 2)
gemm1_kernel() {
    const int m0 = blockIdx.y * 128;
    const int n0 = blockIdx.x * 128;
    float acc[4][8][4];
    gemm_main(g_A1, g_W1, m0, n0, acc);

    const int tid = threadIdx.x, wid = tid >> 5, lane = tid & 31;
    const int wm = (wid >> 1) * 64, wn = (wid & 1) * 64;
    const int gid = lane >> 2, tig = lane & 3;

#pragma unroll
    for (int mf = 0; mf < 4; mf++) {
#pragma unroll
        for (int q2 = 0; q2 < 2; q2++) {
            const int r = m0 + wm + mf * 16 + gid + q2 * 8;
            const int win = r / NTOK;
            const int t = r - win * NTOK;
#pragma unroll
            for (int nf = 0; nf < 8; nf++) {
                const int c = n0 + wn + nf * 8 + tig * 2;
                const int s  = c / 768;
                const int rm = c - s * 768;
                const int h  = rm / 96;
                const int dd = rm - h * 96;
                float v0 = acc[mf][nf][q2 * 2]     + g_b1p[c];
                float v1 = acc[mf][nf][q2 * 2 + 1] + g_b1p[c + 1];
                __nv_bfloat16* base = (s == 0 ? g_Qb : (s == 1 ? g_Kb : g_Vb))
                                      + ((size_t)(win * NH + h) * NTOK + t) * HD + dd;
                *(uint32_t*)base = pk(v0, v1);
            }
        }
    }
}

__global__ void __launch_bounds__(128, 2)
gemm3_kernel(const float* __restrict__ x,
             const float* __restrict__ bias,
             float* __restrict__ out) {
    const int m0 = blockIdx.y * 128;
    const int n0 = blockIdx.x * 128;
    float acc[4][8][4];
    gemm_main(g_Ob, g_W2, m0, n0, acc);

    const int tid = threadIdx.x, wid = tid >> 5, lane = tid & 31;
    const int wm = (wid >> 1) * 64, wn = (wid & 1) * 64;
    const int gid = lane >> 2, tig = lane & 3;

#pragma unroll
    for (int mf = 0; mf < 4; mf++) {
#pragma unroll
        for (int q2 = 0; q2 < 2; q2++) {
            const int r = m0 + wm + mf * 16 + gid + q2 * 8;
            const int xr = map_row(r);
#pragma unroll
            for (int nf = 0; nf < 8; nf++) {
                const int c = n0 + wn + nf * 8 + tig * 2;
                const size_t idx = (size_t)xr * EMB + c;
                float2 xv = *(const float2*)(x + idx);
                out[idx]     = acc[mf][nf][q2 * 2]     + bias[c]     + xv.x;
                out[idx + 1] = acc[mf][nf][q2 * 2 + 1] + bias[c + 1] + xv.y;
            }
        }
    }
}

// ---------------------------------------------------------------------------
// Attention (unchanged champion): grid (2048, 2), 128 threads, 2 CTAs/SM.
// ---------------------------------------------------------------------------
#define KVSTRIDE 208
#define KV_BYTES (224 * KVSTRIDE)
#define SHIFT 40.0f

__global__ void __launch_bounds__(128, 2)
attn_kernel() {
    extern __shared__ __align__(16) char smem[];
    const int wh   = blockIdx.x;
    const int half = blockIdx.y;
    const int tid  = threadIdx.x;
    const uint32_t sb = (uint32_t)__cvta_generic_to_shared(smem);
    const uint32_t Ko = sb, Vo = sb + KV_BYTES;

    const __nv_bfloat16* gq = g_Qb + (size_t)wh * NTOK * HD;
    const __nv_bfloat16* gk = g_Kb + (size_t)wh * NTOK * HD;
    const __nv_bfloat16* gv = g_Vb + (size_t)wh * NTOK * HD;

    for (int i = tid; i < NTOK * 12; i += 128) {
        int t = i / 12, c = i - (i / 12) * 12;
        uint32_t off = (uint32_t)(t * KVSTRIDE + c * 16);
        const size_t g = (size_t)t * HD + c * 8;
        cp16(Ko + off, gk + g);
        cp16(Vo + off, gv + g);
    }
    cp_commit();
    for (int i = tid; i < 28 * 12; i += 128) {
        int t = 196 + i / 12, c = i - (i / 12) * 12;
        uint32_t off = (uint32_t)(t * KVSTRIDE + c * 16);
        uint4 z = make_uint4(0, 0, 0, 0);
        *(uint4*)(smem + off) = z;
        *(uint4*)(smem + KV_BYTES + off) = z;
    }

    const int w = tid >> 5;
    const int lane = tid & 31;
    const int gid = lane >> 2, tig = lane & 3;
    const int m0 = half * 128 + w * 32;
    const bool act = (m0 < NTOK);

    uint32_t aq[2][6][4];
    if (act) {
#pragma unroll
        for (int mt = 0; mt < 2; mt++) {
            const int r0 = m0 + mt * 16 + gid;
            const int r1 = r0 + 8;
#pragma unroll
            for (int kk = 0; kk < 6; kk++) {
                const int col = kk * 16 + tig * 2;
                aq[mt][kk][0] = (r0 < NTOK) ? *(const uint32_t*)(gq + (size_t)r0 * HD + col) : 0u;
                aq[mt][kk][1] = (r1 < NTOK) ? *(const uint32_t*)(gq + (size_t)r1 * HD + col) : 0u;
                aq[mt][kk][2] = (r0 < NTOK) ? *(const uint32_t*)(gq + (size_t)r0 * HD + col + 8) : 0u;
                aq[mt][kk][3] = (r1 < NTOK) ? *(const uint32_t*)(gq + (size_t)r1 * HD + col + 8) : 0u;
            }
        }
    }

    cp_wait<0>();
    __syncthreads();

    if (!act) return;

    float accO[2][12][4];
#pragma unroll
    for (int mt = 0; mt < 2; mt++)
#pragma unroll
        for (int nt = 0; nt < 12; nt++)
#pragma unroll
            for (int q = 0; q < 4; q++) accO[mt][nt][q] = 0.f;

    float rl[2][2] = {{0.f, 0.f}, {0.f, 0.f}};

#pragma unroll 1
    for (int ch = 0; ch < 7; ch++) {
        const int n0 = ch * 32;
        float s[2][4][4];
#pragma unroll
        for (int mt = 0; mt < 2; mt++)
#pragma unroll
            for (int nt = 0; nt < 4; nt++)
#pragma unroll
                for (int q = 0; q < 4; q++) s[mt][nt][q] = 0.f;

#pragma unroll
        for (int kk = 0; kk < 6; kk++) {
            uint32_t kb0[4], kb1[4];
            uint32_t kaddr = Ko + (uint32_t)((n0 + (lane & 7) + ((lane >> 4) << 3)) * KVSTRIDE
                                             + (kk * 2 + ((lane >> 3) & 1)) * 16);
            ldsm4(kb0, kaddr);
            ldsm4(kb1, kaddr + 16 * KVSTRIDE);
#pragma unroll
            for (int mt = 0; mt < 2; mt++) {
                mma_bf16(s[mt][0], aq[mt][kk], kb0[0], kb0[1]);
                mma_bf16(s[mt][1], aq[mt][kk], kb0[2], kb0[3]);
                mma_bf16(s[mt][2], aq[mt][kk], kb1[0], kb1[1]);
                mma_bf16(s[mt][3], aq[mt][kk], kb1[2], kb1[3]);
            }
        }

        if (ch == 6) {
#pragma unroll
            for (int mt = 0; mt < 2; mt++)
#pragma unroll
                for (int nt = 0; nt < 4; nt++)
#pragma unroll
                    for (int q = 0; q < 4; q++) {
                        int col = n0 + nt * 8 + tig * 2 + (q & 1);
                        if (col >= NTOK) s[mt][nt][q] = -1e30f;
                    }
        }

#pragma unroll
        for (int mt = 0; mt < 2; mt++) {
#pragma unroll
            for (int hf = 0; hf < 2; hf++) {
                float ls = 0.f;
#pragma unroll
                for (int nt = 0; nt < 4; nt++) {
                    float p0 = __expf(s[mt][nt][hf * 2]     - SHIFT);
                    float p1 = __expf(s[mt][nt][hf * 2 + 1] - SHIFT);
                    s[mt][nt][hf * 2]     = p0;
                    s[mt][nt][hf * 2 + 1] = p1;
                    ls += p0 + p1;
                }
                rl[mt][hf] += ls;
            }
        }

#pragma unroll
        for (int kk = 0; kk < 2; kk++) {
            uint32_t ap[2][4];
#pragma unroll
            for (int mt = 0; mt < 2; mt++) {
                ap[mt][0] = pk(s[mt][kk * 2][0], s[mt][kk * 2][1]);
                ap[mt][1] = pk(s[mt][kk * 2][2], s[mt][kk * 2][3]);
                ap[mt][2] = pk(s[mt][kk * 2 + 1][0], s[mt][kk * 2 + 1][1]);
                ap[mt][3] = pk(s[mt][kk * 2 + 1][2], s[mt][kk * 2 + 1][3]);
            }
#pragma unroll
            for (int u = 0; u < 6; u++) {
                uint32_t vb[4];
                ldsm4t(vb, Vo + (uint32_t)((n0 + kk * 16 + (lane & 7) + (((lane >> 3) & 1) << 3)) * KVSTRIDE
                                           + (u * 2 + (lane >> 4)) * 16));
#pragma unroll
                for (int mt = 0; mt < 2; mt++) {
                    mma_bf16(accO[mt][u * 2],     ap[mt], vb[0], vb[1]);
                    mma_bf16(accO[mt][u * 2 + 1], ap[mt], vb[2], vb[3]);
                }
            }
        }
    }

    const int win = wh >> 3;
    const int h   = wh & 7;
#pragma unroll
    for (int mt = 0; mt < 2; mt++) {
#pragma unroll
        for (int hf = 0; hf < 2; hf++) {
            float tot = rl[mt][hf];
            tot += __shfl_xor_sync(0xffffffff, tot, 1);
            tot += __shfl_xor_sync(0xffffffff, tot, 2);
            const int t = m0 + mt * 16 + gid + hf * 8;
            if (t < NTOK) {
                const float inv = 1.0f / (tot * 27.712812921102035f);
                uint32_t* op = (uint32_t*)(g_Ob + ((size_t)(win * NTOK + t)) * EMB
                                           + h * HD + tig * 2);
#pragma unroll
                for (int nt = 0; nt < 12; nt++) {
                    op[nt * 4] = pk(accO[mt][nt][hf * 2] * inv,
                                    accO[mt][nt][hf * 2 + 1] * inv);
                }
            }
        }
    }
}

// ---------------------------------------------------------------------------
extern "C" void kernel_launch(void* const* d_in, const int* in_sizes, int n_in,
                              void* d_out, int out_size) {
    const float* x      = (const float*)d_in[0];
    const float* w_qkv  = (const float*)d_in[1];
    const float* b_qkv  = (const float*)d_in[2];
    const float* w_proj = (const float*)d_in[3];
    const float* b_proj = (const float*)d_in[4];
    float* out = (float*)d_out;

    prep_kernel<<<PB1 + PB2 + PB3, 256>>>(x, w_qkv, b_qkv, w_proj);

    cudaFuncSetAttribute(gemm1_kernel, cudaFuncAttributeMaxDynamicSharedMemorySize, GSMEM);
    gemm1_kernel<<<dim3(QKVC / 128, MROWS / 128), 128, GSMEM>>>();

    const int asmem = 2 * KV_BYTES;
    cudaFuncSetAttribute(attn_kernel, cudaFuncAttributeMaxDynamicSharedMemorySize, asmem);
    attn_kernel<<<dim3(NWIN * NH, 2), 128, asmem>>>();

    cudaFuncSetAttribute(gemm3_kernel, cudaFuncAttributeMaxDynamicSharedMemorySize, GSMEM);
    gemm3_kernel<<<dim3(EMB / 128, MROWS / 128), 128, GSMEM>>>(x, b_proj, out);
}

// round 17
// speedup vs baseline: 1.1639x; 1.0553x over previous
#include <cuda_runtime.h>
#include <cuda_bf16.h>
#include <cstdint>

// ---------------------------------------------------------------------------
// WindowedMultiHeadAttention — bf16 mma.sync champion GEMM config +
// smem-staged coalesced epilogues (alignment-fixed: stride 68 u32).
// ---------------------------------------------------------------------------

#define EMB   768
#define NH    8
#define HD    96
#define NWIN  256
#define NTOK  196
#define MROWS (NWIN * NTOK)   // 50176
#define QKVC  (3 * EMB)       // 2304

#define PB1 (MROWS * 96 / 256)
#define PB2 (QKVC * 96 / 256)
#define PB3 (EMB * 96 / 256)

__device__ __align__(16) __nv_bfloat16 g_Qb[NWIN * NH * NTOK * HD];
__device__ __align__(16) __nv_bfloat16 g_Kb[NWIN * NH * NTOK * HD];
__device__ __align__(16) __nv_bfloat16 g_Vb[NWIN * NH * NTOK * HD];
__device__ __align__(16) __nv_bfloat16 g_A1[MROWS * EMB];
__device__ __align__(16) __nv_bfloat16 g_W1[QKVC * EMB];    // permuted [s][h][dd], K-major
__device__ __align__(16) __nv_bfloat16 g_W2[EMB * EMB];
__device__ __align__(16) __nv_bfloat16 g_Ob[MROWS * EMB];
__device__ float g_b1p[QKVC];

__device__ __forceinline__ int map_row(int r) {
    int win = r / NTOK;
    int t   = r - win * NTOK;
    int b   = win >> 4;
    int wr  = win & 15;
    int wh  = wr >> 2;
    int ww  = wr & 3;
    int i   = t / 14;
    int j   = t - i * 14;
    return (b * 56 + wh * 14 + i) * 56 + (ww * 14 + j);
}

__device__ __forceinline__ uint32_t pk(float x, float y) {
    __nv_bfloat162 h = __floats2bfloat162_rn(x, y);
    return *reinterpret_cast<uint32_t*>(&h);
}

__device__ __forceinline__ void cp16(uint32_t dst, const void* src) {
    asm volatile("cp.async.cg.shared.global [%0], [%1], 16;" :: "r"(dst), "l"(src));
}
__device__ __forceinline__ void cp_commit() {
    asm volatile("cp.async.commit_group;");
}
template <int N>
__device__ __forceinline__ void cp_wait() {
    asm volatile("cp.async.wait_group %0;" :: "n"(N));
}

__device__ __forceinline__ void ldsm4(uint32_t* r, uint32_t addr) {
    asm volatile("ldmatrix.sync.aligned.m8n8.x4.shared.b16 {%0,%1,%2,%3}, [%4];"
                 : "=r"(r[0]), "=r"(r[1]), "=r"(r[2]), "=r"(r[3]) : "r"(addr));
}
__device__ __forceinline__ void ldsm4t(uint32_t* r, uint32_t addr) {
    asm volatile("ldmatrix.sync.aligned.m8n8.x4.trans.shared.b16 {%0,%1,%2,%3}, [%4];"
                 : "=r"(r[0]), "=r"(r[1]), "=r"(r[2]), "=r"(r[3]) : "r"(addr));
}

__device__ __forceinline__ void mma_bf16(float* d, const uint32_t* a, uint32_t b0, uint32_t b1) {
    asm volatile(
        "mma.sync.aligned.m16n8k16.row.col.f32.bf16.bf16.f32 "
        "{%0,%1,%2,%3}, {%4,%5,%6,%7}, {%8,%9}, {%0,%1,%2,%3};"
        : "+f"(d[0]), "+f"(d[1]), "+f"(d[2]), "+f"(d[3])
        : "r"(a[0]), "r"(a[1]), "r"(a[2]), "r"(a[3]), "r"(b0), "r"(b1));
}

// ---------------------------------------------------------------------------
// merged prep kernel
// ---------------------------------------------------------------------------
__global__ void prep_kernel(const float* __restrict__ x,
                            const float* __restrict__ w_qkv,
                            const float* __restrict__ b_qkv,
                            const float* __restrict__ w_proj) {
    const int blk = blockIdx.x;
    const int tid = threadIdx.x;

    if (blk < PB1) {
        int g  = blk * 256 + tid;
        int r  = g / 96;
        int kc = (g - r * 96) * 8;
        const float* s = x + (size_t)map_row(r) * EMB + kc;
        float4 v0 = *(const float4*)s;
        float4 v1 = *(const float4*)(s + 4);
        uint4 u;
        u.x = pk(v0.x, v0.y); u.y = pk(v0.z, v0.w);
        u.z = pk(v1.x, v1.y); u.w = pk(v1.z, v1.w);
        *(uint4*)(g_A1 + (size_t)r * EMB + kc) = u;
    } else if (blk < PB1 + PB2) {
        int g  = (blk - PB1) * 256 + tid;
        int c  = g / 96;
        int k0 = (g - c * 96) * 8;
        int h  = c / 288;
        int rm = c - h * 288;
        int dd = rm / 3;
        int s  = rm - dd * 3;
        int cp_ = s * 768 + h * 96 + dd;
        float v[8];
#pragma unroll
        for (int i = 0; i < 8; i++) v[i] = w_qkv[(size_t)(k0 + i) * QKVC + c];
        uint4 u;
        u.x = pk(v[0], v[1]); u.y = pk(v[2], v[3]);
        u.z = pk(v[4], v[5]); u.w = pk(v[6], v[7]);
        *(uint4*)(g_W1 + (size_t)cp_ * EMB + k0) = u;
        if (g < QKVC) {
            int ch  = g / 288;
            int crm = g - ch * 288;
            int cdd = crm / 3;
            int cs  = crm - cdd * 3;
            g_b1p[cs * 768 + ch * 96 + cdd] = b_qkv[g];
        }
    } else {
        int g  = (blk - PB1 - PB2) * 256 + tid;
        int c  = g / 96;
        int k0 = (g - c * 96) * 8;
        float v[8];
#pragma unroll
        for (int i = 0; i < 8; i++) v[i] = w_proj[(size_t)(k0 + i) * EMB + c];
        uint4 u;
        u.x = pk(v[0], v[1]); u.y = pk(v[2], v[3]);
        u.z = pk(v[4], v[5]); u.w = pk(v[6], v[7]);
        *(uint4*)(g_W2 + (size_t)c * EMB + k0) = u;
    }
}

// ---------------------------------------------------------------------------
// bf16 GEMM mainloop (champion): C[128x128], 4 warps of 64x64, BK=64, 3-stage
// ---------------------------------------------------------------------------
#define STG 32768
#define GSMEM (3 * STG + 128)

__device__ __forceinline__ void g_fill(uint32_t sb, int stage,
                                       const __nv_bfloat16* __restrict__ A,
                                       const __nv_bfloat16* __restrict__ B,
                                       int m0, int n0, int kc, int tid) {
    uint32_t abase = sb + stage * STG;
    uint32_t bbase = abase + 16384;
#pragma unroll
    for (int i = 0; i < 8; i++) {
        int idx = tid + i * 128;
        int r = idx >> 3, c = idx & 7;
        uint32_t sw = (uint32_t)(r * 128 + ((c ^ (r & 7)) << 4));
        cp16(abase + sw, A + (size_t)(m0 + r) * EMB + kc + c * 8);
    }
#pragma unroll
    for (int i = 0; i < 8; i++) {
        int idx = tid + i * 128;
        int r = idx >> 3, c = idx & 7;
        uint32_t sw = (uint32_t)(r * 128 + ((c ^ (r & 7)) << 4));
        cp16(bbase + sw, B + (size_t)(n0 + r) * EMB + kc + c * 8);
    }
}

__device__ __forceinline__ void gemm_main(const __nv_bfloat16* __restrict__ A,
                                          const __nv_bfloat16* __restrict__ B,
                                          int m0, int n0, uint32_t sb,
                                          float (&acc)[4][8][4]) {
    const int tid = threadIdx.x;

#pragma unroll
    for (int i = 0; i < 4; i++)
#pragma unroll
        for (int j = 0; j < 8; j++)
#pragma unroll
            for (int q = 0; q < 4; q++) acc[i][j][q] = 0.f;

    const int wid = tid >> 5, lane = tid & 31;
    const int wm = (wid >> 1) * 64;
    const int wn = (wid & 1) * 64;
    const int lr = lane & 15;
    const uint32_t khx = (uint32_t)((lane >> 4) << 4);

    uint32_t arel[4], brel[4];
#pragma unroll
    for (int mf = 0; mf < 4; mf++) {
        int r = wm + mf * 16 + lr;
        arel[mf] = ((uint32_t)(r * 128 + ((r & 7) << 4))) ^ khx;
    }
#pragma unroll
    for (int nt = 0; nt < 4; nt++) {
        int r = wn + nt * 16 + lr;
        brel[nt] = ((uint32_t)(16384 + r * 128 + ((r & 7) << 4))) ^ khx;
    }

    g_fill(sb, 0, A, B, m0, n0, 0, tid);  cp_commit();
    g_fill(sb, 1, A, B, m0, n0, 64, tid); cp_commit();

    int st = 0, fs = 2;
#pragma unroll 1
    for (int it = 0; it < 12; it++) {
        cp_wait<1>();
        __syncthreads();
        if (it + 2 < 12) g_fill(sb, fs, A, B, m0, n0, (it + 2) * 64, tid);
        cp_commit();
        const uint32_t stb = sb + (uint32_t)st * STG;

#pragma unroll
        for (int kk = 0; kk < 4; kk++) {
            const uint32_t kx = (uint32_t)(kk << 5);
            uint32_t a[4][4], b[4][4];
#pragma unroll
            for (int mf = 0; mf < 4; mf++) ldsm4(a[mf], (stb + arel[mf]) ^ kx);
#pragma unroll
            for (int nt = 0; nt < 4; nt++) ldsm4(b[nt], (stb + brel[nt]) ^ kx);
#pragma unroll
            for (int mf = 0; mf < 4; mf++)
#pragma unroll
                for (int nt = 0; nt < 4; nt++) {
                    mma_bf16(acc[mf][nt * 2],     a[mf], b[nt][0], b[nt][2]);
                    mma_bf16(acc[mf][nt * 2 + 1], a[mf], b[nt][1], b[nt][3]);
                }
        }
        st = (st == 2) ? 0 : st + 1;
        fs = (fs == 2) ? 0 : fs + 1;
    }
    __syncthreads();   // all warps done with stage buffers (epilogue reuses smem)
}

// ---------------------------------------------------------------------------
// GEMM 1: smem-staged coalesced epilogue into Q/K/V
// stage layout: u32[128][68] (bf16x2); 68*4 = 272 B row stride (16B-aligned)
// ---------------------------------------------------------------------------
#define EP1STR 68

__global__ void __launch_bounds__(128, 2)
gemm1_kernel() {
    extern __shared__ __align__(16) char dsm[];
    uint32_t sb0 = (uint32_t)__cvta_generic_to_shared(dsm);
    const uint32_t sb = (sb0 + 127) & ~127u;

    const int m0 = blockIdx.y * 128;
    const int n0 = blockIdx.x * 128;
    float acc[4][8][4];
    gemm_main(g_A1, g_W1, m0, n0, sb, acc);

    const int tid = threadIdx.x, wid = tid >> 5, lane = tid & 31;
    const int wm = (wid >> 1) * 64, wn = (wid & 1) * 64;
    const int gid = lane >> 2, tig = lane & 3;

    uint32_t* ep = (uint32_t*)dsm + ((sb - sb0) >> 2);   // 128B-aligned

    // stage: bias + pack bf16x2 -> ep[lr][lc/2]
#pragma unroll
    for (int mf = 0; mf < 4; mf++) {
#pragma unroll
        for (int q2 = 0; q2 < 2; q2++) {
            const int lr = wm + mf * 16 + gid + q2 * 8;
#pragma unroll
            for (int nf = 0; nf < 8; nf++) {
                const int lc = wn + nf * 8 + tig * 2;
                const int c  = n0 + lc;
                float v0 = acc[mf][nf][q2 * 2]     + g_b1p[c];
                float v1 = acc[mf][nf][q2 * 2 + 1] + g_b1p[c + 1];
                ep[lr * EP1STR + (lc >> 1)] = pk(v0, v1);
            }
        }
    }
    __syncthreads();

    // cooperative coalesced store: 2048 chunks of 16B (8 bf16)
    const int s = n0 / 768;                      // constant per tile
    __nv_bfloat16* gbase = (s == 0 ? g_Qb : (s == 1 ? g_Kb : g_Vb));
    const int nrm = n0 - s * 768;
#pragma unroll
    for (int j = 0; j < 16; j++) {
        const int idx = tid + j * 128;           // 0..2047
        const int lr  = idx >> 4;
        const int pos = idx & 15;
        const int r   = m0 + lr;
        const int win = r / NTOK;
        const int t   = r - win * NTOK;
        const int rm  = nrm + pos * 8;
        const int h   = rm / 96;
        const int dd  = rm - h * 96;
        uint4 v = *(uint4*)(ep + lr * EP1STR + pos * 4);
        *(uint4*)(gbase + ((size_t)(win * NH + h) * NTOK + t) * HD + dd) = v;
    }
}

// ---------------------------------------------------------------------------
// GEMM 3: smem-staged fully-coalesced epilogue (one 512B row per warp step)
// stage layout: float[128][132]; 132*4 = 528 B row stride (16B-aligned)
// ---------------------------------------------------------------------------
__global__ void __launch_bounds__(128, 2)
gemm3_kernel(const float* __restrict__ x,
             const float* __restrict__ bias,
             float* __restrict__ out) {
    extern __shared__ __align__(16) char dsm[];
    uint32_t sb0 = (uint32_t)__cvta_generic_to_shared(dsm);
    const uint32_t sb = (sb0 + 127) & ~127u;

    const int m0 = blockIdx.y * 128;
    const int n0 = blockIdx.x * 128;
    float acc[4][8][4];
    gemm_main(g_Ob, g_W2, m0, n0, sb, acc);

    const int tid = threadIdx.x, wid = tid >> 5, lane = tid & 31;
    const int wm = (wid >> 1) * 64, wn = (wid & 1) * 64;
    const int gid = lane >> 2, tig = lane & 3;

    float* ep = (float*)dsm + ((sb - sb0) >> 2);

    // stage raw accumulators
#pragma unroll
    for (int mf = 0; mf < 4; mf++) {
#pragma unroll
        for (int q2 = 0; q2 < 2; q2++) {
            const int lr = wm + mf * 16 + gid + q2 * 8;
#pragma unroll
            for (int nf = 0; nf < 8; nf++) {
                const int lc = wn + nf * 8 + tig * 2;
                float2 v = make_float2(acc[mf][nf][q2 * 2], acc[mf][nf][q2 * 2 + 1]);
                *(float2*)(ep + lr * 132 + lc) = v;
            }
        }
    }
    __syncthreads();

    // cooperative store: warp writes one full 512B row segment per step
#pragma unroll
    for (int j = 0; j < 32; j++) {
        const int idx = tid + j * 128;           // 0..4095
        const int lr  = idx >> 5;
        const int pos = idx & 31;
        const int r   = m0 + lr;
        const int xr  = map_row(r);
        const int c   = n0 + pos * 4;
        float4 a = *(float4*)(ep + lr * 132 + pos * 4);
        float4 bv = *(const float4*)(bias + c);
        float4 xv = *(const float4*)(x + (size_t)xr * EMB + c);
        float4 o;
        o.x = a.x + bv.x + xv.x;
        o.y = a.y + bv.y + xv.y;
        o.z = a.z + bv.z + xv.z;
        o.w = a.w + bv.w + xv.w;
        *(float4*)(out + (size_t)xr * EMB + c) = o;
    }
}

// ---------------------------------------------------------------------------
// Attention (unchanged champion): grid (2048, 2), 128 threads, 2 CTAs/SM.
// ---------------------------------------------------------------------------
#define KVSTRIDE 208
#define KV_BYTES (224 * KVSTRIDE)
#define SHIFT 40.0f

__global__ void __launch_bounds__(128, 2)
attn_kernel() {
    extern __shared__ __align__(16) char smem[];
    const int wh   = blockIdx.x;
    const int half = blockIdx.y;
    const int tid  = threadIdx.x;
    const uint32_t sb = (uint32_t)__cvta_generic_to_shared(smem);
    const uint32_t Ko = sb, Vo = sb + KV_BYTES;

    const __nv_bfloat16* gq = g_Qb + (size_t)wh * NTOK * HD;
    const __nv_bfloat16* gk = g_Kb + (size_t)wh * NTOK * HD;
    const __nv_bfloat16* gv = g_Vb + (size_t)wh * NTOK * HD;

    for (int i = tid; i < NTOK * 12; i += 128) {
        int t = i / 12, c = i - (i / 12) * 12;
        uint32_t off = (uint32_t)(t * KVSTRIDE + c * 16);
        const size_t g = (size_t)t * HD + c * 8;
        cp16(Ko + off, gk + g);
        cp16(Vo + off, gv + g);
    }
    cp_commit();
    for (int i = tid; i < 28 * 12; i += 128) {
        int t = 196 + i / 12, c = i - (i / 12) * 12;
        uint32_t off = (uint32_t)(t * KVSTRIDE + c * 16);
        uint4 z = make_uint4(0, 0, 0, 0);
        *(uint4*)(smem + off) = z;
        *(uint4*)(smem + KV_BYTES + off) = z;
    }

    const int w = tid >> 5;
    const int lane = tid & 31;
    const int gid = lane >> 2, tig = lane & 3;
    const int m0 = half * 128 + w * 32;
    const bool act = (m0 < NTOK);

    uint32_t aq[2][6][4];
    if (act) {
#pragma unroll
        for (int mt = 0; mt < 2; mt++) {
            const int r0 = m0 + mt * 16 + gid;
            const int r1 = r0 + 8;
#pragma unroll
            for (int kk = 0; kk < 6; kk++) {
                const int col = kk * 16 + tig * 2;
                aq[mt][kk][0] = (r0 < NTOK) ? *(const uint32_t*)(gq + (size_t)r0 * HD + col) : 0u;
                aq[mt][kk][1] = (r1 < NTOK) ? *(const uint32_t*)(gq + (size_t)r1 * HD + col) : 0u;
                aq[mt][kk][2] = (r0 < NTOK) ? *(const uint32_t*)(gq + (size_t)r0 * HD + col + 8) : 0u;
                aq[mt][kk][3] = (r1 < NTOK) ? *(const uint32_t*)(gq + (size_t)r1 * HD + col + 8) : 0u;
            }
        }
    }

    cp_wait<0>();
    __syncthreads();

    if (!act) return;

    float accO[2][12][4];
#pragma unroll
    for (int mt = 0; mt < 2; mt++)
#pragma unroll
        for (int nt = 0; nt < 12; nt++)
#pragma unroll
            for (int q = 0; q < 4; q++) accO[mt][nt][q] = 0.f;

    float rl[2][2] = {{0.f, 0.f}, {0.f, 0.f}};

#pragma unroll 1
    for (int ch = 0; ch < 7; ch++) {
        const int n0 = ch * 32;
        float s[2][4][4];
#pragma unroll
        for (int mt = 0; mt < 2; mt++)
#pragma unroll
            for (int nt = 0; nt < 4; nt++)
#pragma unroll
                for (int q = 0; q < 4; q++) s[mt][nt][q] = 0.f;

#pragma unroll
        for (int kk = 0; kk < 6; kk++) {
            uint32_t kb0[4], kb1[4];
            uint32_t kaddr = Ko + (uint32_t)((n0 + (lane & 7) + ((lane >> 4) << 3)) * KVSTRIDE
                                             + (kk * 2 + ((lane >> 3) & 1)) * 16);
            ldsm4(kb0, kaddr);
            ldsm4(kb1, kaddr + 16 * KVSTRIDE);
#pragma unroll
            for (int mt = 0; mt < 2; mt++) {
                mma_bf16(s[mt][0], aq[mt][kk], kb0[0], kb0[1]);
                mma_bf16(s[mt][1], aq[mt][kk], kb0[2], kb0[3]);
                mma_bf16(s[mt][2], aq[mt][kk], kb1[0], kb1[1]);
                mma_bf16(s[mt][3], aq[mt][kk], kb1[2], kb1[3]);
            }
        }

        if (ch == 6) {
#pragma unroll
            for (int mt = 0; mt < 2; mt++)
#pragma unroll
                for (int nt = 0; nt < 4; nt++)
#pragma unroll
                    for (int q = 0; q < 4; q++) {
                        int col = n0 + nt * 8 + tig * 2 + (q & 1);
                        if (col >= NTOK) s[mt][nt][q] = -1e30f;
                    }
        }

#pragma unroll
        for (int mt = 0; mt < 2; mt++) {
#pragma unroll
            for (int hf = 0; hf < 2; hf++) {
                float ls = 0.f;
#pragma unroll
                for (int nt = 0; nt < 4; nt++) {
                    float p0 = __expf(s[mt][nt][hf * 2]     - SHIFT);
                    float p1 = __expf(s[mt][nt][hf * 2 + 1] - SHIFT);
                    s[mt][nt][hf * 2]     = p0;
                    s[mt][nt][hf * 2 + 1] = p1;
                    ls += p0 + p1;
                }
                rl[mt][hf] += ls;
            }
        }

#pragma unroll
        for (int kk = 0; kk < 2; kk++) {
            uint32_t ap[2][4];
#pragma unroll
            for (int mt = 0; mt < 2; mt++) {
                ap[mt][0] = pk(s[mt][kk * 2][0], s[mt][kk * 2][1]);
                ap[mt][1] = pk(s[mt][kk * 2][2], s[mt][kk * 2][3]);
                ap[mt][2] = pk(s[mt][kk * 2 + 1][0], s[mt][kk * 2 + 1][1]);
                ap[mt][3] = pk(s[mt][kk * 2 + 1][2], s[mt][kk * 2 + 1][3]);
            }
#pragma unroll
            for (int u = 0; u < 6; u++) {
                uint32_t vb[4];
                ldsm4t(vb, Vo + (uint32_t)((n0 + kk * 16 + (lane & 7) + (((lane >> 3) & 1) << 3)) * KVSTRIDE
                                           + (u * 2 + (lane >> 4)) * 16));
#pragma unroll
                for (int mt = 0; mt < 2; mt++) {
                    mma_bf16(accO[mt][u * 2],     ap[mt], vb[0], vb[1]);
                    mma_bf16(accO[mt][u * 2 + 1], ap[mt], vb[2], vb[3]);
                }
            }
        }
    }

    const int win = wh >> 3;
    const int h   = wh & 7;
#pragma unroll
    for (int mt = 0; mt < 2; mt++) {
#pragma unroll
        for (int hf = 0; hf < 2; hf++) {
            float tot = rl[mt][hf];
            tot += __shfl_xor_sync(0xffffffff, tot, 1);
            tot += __shfl_xor_sync(0xffffffff, tot, 2);
            const int t = m0 + mt * 16 + gid + hf * 8;
            if (t < NTOK) {
                const float inv = 1.0f / (tot * 27.712812921102035f);
                uint32_t* op = (uint32_t*)(g_Ob + ((size_t)(win * NTOK + t)) * EMB
                                           + h * HD + tig * 2);
#pragma unroll
                for (int nt = 0; nt < 12; nt++) {
                    op[nt * 4] = pk(accO[mt][nt][hf * 2] * inv,
                                    accO[mt][nt][hf * 2 + 1] * inv);
                }
            }
        }
    }
}

// ---------------------------------------------------------------------------
extern "C" void kernel_launch(void* const* d_in, const int* in_sizes, int n_in,
                              void* d_out, int out_size) {
    const float* x      = (const float*)d_in[0];
    const float* w_qkv  = (const float*)d_in[1];
    const float* b_qkv  = (const float*)d_in[2];
    const float* w_proj = (const float*)d_in[3];
    const float* b_proj = (const float*)d_in[4];
    float* out = (float*)d_out;

    prep_kernel<<<PB1 + PB2 + PB3, 256>>>(x, w_qkv, b_qkv, w_proj);

    cudaFuncSetAttribute(gemm1_kernel, cudaFuncAttributeMaxDynamicSharedMemorySize, GSMEM);
    gemm1_kernel<<<dim3(QKVC / 128, MROWS / 128), 128, GSMEM>>>();

    const int asmem = 2 * KV_BYTES;
    cudaFuncSetAttribute(attn_kernel, cudaFuncAttributeMaxDynamicSharedMemorySize, asmem);
    attn_kernel<<<dim3(NWIN * NH, 2), 128, asmem>>>();

    cudaFuncSetAttribute(gemm3_kernel, cudaFuncAttributeMaxDynamicSharedMemorySize, GSMEM);
    gemm3_kernel<<<dim3(EMB / 128, MROWS / 128), 128, GSMEM>>>(x, b_proj, out);
}